// round 12
// baseline (speedup 1.0000x reference)
#include <cuda_runtime.h>
#include <cuda_bf16.h>
#include <cstdint>

#define NB 512
#define DD 128
#define WW 512
#define TT 512
#define NTHR 512

// float-indexed SMEM layout (bf16 counts / 2 = floats!)
#define O_W1 0                          // 64x132 f32 (tf32)      8448 f
#define O_AM (O_W1+64*132)              // 16x132 f32             2112 f
#define O_B  (O_AM+16*132)              // 144 biases
#define O_TS (O_B+144)                  // 512 ts
#define O_MB (O_TS+512)                 // 8 mbarriers = 16 f
#define O_Z  (O_MB+16)                  // per-wave 16x132 f32 (2112 f each)
#define O_PT (O_Z+2*2112)               // per-wave 16x68 f32 (1088 f each)
#define O_W2H (O_PT+2*1088)             // bf16 64x520 = 16640 f
#define O_W3H (O_W2H+16640)             // bf16 16x520 = 4160 f
#define O_KS  (O_W3H+4160)              // per-wave 5x16x128 bf16 = 5120 f each
#define O_SG  (O_KS+2*5120)             // per-wave 4x(16x136) bf16 = 4352 f each
#define SMF   (O_SG+2*4352)             // 57376 f = 229504 B

__device__ __align__(16) __nv_bfloat16 g_h1[2][NB*WW];
__device__ __align__(16) __nv_bfloat16 g_h2[2][NB*WW];
__device__ __align__(16) float g_y[NB*DD];

__constant__ float c_AT[6][5] = {
    {0.f,0.f,0.f,0.f,0.f},
    {0.161f,0.f,0.f,0.f,0.f},
    {-0.008480655492356989f,0.335480655492357f,0.f,0.f,0.f},
    {2.8971530571054935f,-6.359448489975075f,4.3622954328695815f,0.f,0.f},
    {5.325864828439257f,-11.748883564062828f,7.4955393428898365f,-0.09249506636175525f,0.f},
    {5.86145544294642f,-12.92096931784711f,8.159367898576159f,-0.071584973281401f,-0.028269050394068383f}};
__constant__ float c_BT[6] = {0.09646076681806523f,0.01f,0.4798896504144996f,
                              1.379008574103742f,-3.290069515436081f,2.324710524099774f};

__device__ __forceinline__ float f2tf32(float x){
    unsigned u; asm("cvt.rna.tf32.f32 %0,%1;":"=r"(u):"f"(x)); return __uint_as_float(u);}
__device__ __forceinline__ float ftanh(float x){
    float e = exp2f(2.885390081777927f * x);
    return 1.0f - __fdividef(2.0f, e + 1.0f);}
__device__ __forceinline__ unsigned pack_bf2(float lo,float hi){
    unsigned r; asm("cvt.rn.bf16x2.f32 %0,%1,%2;":"=r"(r):"f"(hi),"f"(lo)); return r;}
__device__ __forceinline__ void mma8(float* c,const unsigned* a,const unsigned* b){
    asm volatile("mma.sync.aligned.m16n8k8.row.col.f32.tf32.tf32.f32 "
        "{%0,%1,%2,%3},{%4,%5,%6,%7},{%8,%9},{%0,%1,%2,%3};"
        :"+f"(c[0]),"+f"(c[1]),"+f"(c[2]),"+f"(c[3])
        :"r"(a[0]),"r"(a[1]),"r"(a[2]),"r"(a[3]),"r"(b[0]),"r"(b[1]));}
__device__ __forceinline__ void mmab(float* c,const unsigned* a,const unsigned* b){
    asm volatile("mma.sync.aligned.m16n8k16.row.col.f32.bf16.bf16.f32 "
        "{%0,%1,%2,%3},{%4,%5,%6,%7},{%8,%9},{%0,%1,%2,%3};"
        :"+f"(c[0]),"+f"(c[1]),"+f"(c[2]),"+f"(c[3])
        :"r"(a[0]),"r"(a[1]),"r"(a[2]),"r"(a[3]),"r"(b[0]),"r"(b[1]));}
__device__ __forceinline__ unsigned sma(const void* p){
    return (unsigned)__cvta_generic_to_shared(p);}
__device__ __forceinline__ void ldsm4(unsigned r[4], const void* p){
    asm volatile("ldmatrix.sync.aligned.m8n8.x4.shared.b16 {%0,%1,%2,%3},[%4];"
        :"=r"(r[0]),"=r"(r[1]),"=r"(r[2]),"=r"(r[3]):"r"(sma(p)));}
__device__ __forceinline__ void ldsm2(unsigned r[2], const void* p){
    asm volatile("ldmatrix.sync.aligned.m8n8.x2.shared.b16 {%0,%1},[%2];"
        :"=r"(r[0]),"=r"(r[1]):"r"(sma(p)));}
__device__ __forceinline__ void cpa(uint32_t d,const void* s){
    asm volatile("cp.async.cg.shared.global [%0],[%1],16;"::"r"(d),"l"(s):"memory");}
__device__ __forceinline__ void cpc(){asm volatile("cp.async.commit_group;":::"memory");}
__device__ __forceinline__ void nbar(int id){
    asm volatile("bar.sync %0,256;"::"r"(id):"memory");}
__device__ __forceinline__ void fgpu(){
    asm volatile("fence.acq_rel.gpu;":::"memory");}
__device__ __forceinline__ void mbinit(uint32_t a,unsigned c){
    asm volatile("mbarrier.init.shared.b64 [%0],%1;"::"r"(a),"r"(c):"memory");}
__device__ __forceinline__ void mbarr_remote(uint32_t la,unsigned rr){
    uint32_t ra;
    asm volatile("mapa.shared::cluster.u32 %0,%1,%2;":"=r"(ra):"r"(la),"r"(rr));
    asm volatile("mbarrier.arrive.release.cluster.shared::cluster.b64 _,[%0];"
                 ::"r"(ra):"memory");}
__device__ __forceinline__ void mbwait(uint32_t a,unsigned ph){
    unsigned done;
    do{ asm volatile("{\n\t.reg .pred p;\n\t"
        "mbarrier.try_wait.parity.acquire.cluster.shared::cta.b64 p,[%1],%2,0x989680;\n\t"
        "selp.b32 %0,1,0,p;\n\t}":"=r"(done):"r"(a),"r"(ph):"memory");
    }while(!done);}
__device__ __forceinline__ void stclu(uint32_t laddr,unsigned rr,unsigned v){
    uint32_t ra;
    asm volatile("mapa.shared::cluster.u32 %0,%1,%2;":"=r"(ra):"r"(laddr),"r"(rr));
    asm volatile("st.shared::cluster.u32 [%0],%1;"::"r"(ra),"r"(v):"memory");}

// tf32 m16n16: A rows 0-15, 64 K-cols from koff
__device__ __forceinline__ void mmaT16(const float* A,int lda,const float* B,int ldb,
        float acc[2][4],int wn,int koff,int lane){
    const float* ap = A + (lane&15)*lda + ((lane>>4)<<2) + koff;
    const float* bp = B + (wn+(lane&7)+((lane>>4)<<3))*ldb + (((lane>>3)&1)<<2) + koff;
#pragma unroll
    for(int kk=0;kk<64;kk+=8){ unsigned a[4],b[4];
        ldsm4(a,ap+kk); ldsm4(b,bp+kk);
        mma8(acc[0],a,b); mma8(acc[1],a,b+2);}}

// tf32 m16n8: 32 K-cols from koff
__device__ __forceinline__ void mmaT8(const float* A,int lda,const float* B,int ldb,
        float acc[4],int wn8,int koff,int lane){
    const float* ap = A + (lane&15)*lda + ((lane>>4)<<2) + koff;
    const float* bp = B + (wn8+(lane&7))*ldb + (((lane>>3)&1)<<2) + koff;
#pragma unroll
    for(int kk=0;kk<32;kk+=8){ unsigned a[4],b[2];
        ldsm4(a,ap+kk); ldsm2(b,bp+kk);
        mma8(acc,a,b);}}

// bf16 m16n16, nk k16-steps
__device__ __forceinline__ void mmaB16(const __nv_bfloat16* A,int lda,
        const __nv_bfloat16* B,int ldb,float acc[2][4],int wn,
        int koffA,int koffB,int lane,int nk){
    const __nv_bfloat16* ap = A + (lane&15)*lda + ((lane>>4)<<3) + koffA;
    const __nv_bfloat16* bp = B + (wn+(lane&7)+((lane>>4)<<3))*ldb + (((lane>>3)&1)<<3) + koffB;
#pragma unroll
    for(int s=0;s<nk;s++){ unsigned a[4],b[4];
        ldsm4(a,ap+s*16); ldsm4(b,bp+s*16);
        mmab(acc[0],a,b); mmab(acc[1],a,b+2);}}

// bf16 m16n8, nk k16-steps
__device__ __forceinline__ void mmaB8(const __nv_bfloat16* A,int lda,
        const __nv_bfloat16* B,int ldb,float acc[4],int wn8,
        int koffA,int koffB,int lane,int nk){
    const __nv_bfloat16* ap = A + (lane&15)*lda + ((lane>>4)<<3) + koffA;
    const __nv_bfloat16* bp = B + (wn8+(lane&7))*ldb + (((lane>>3)&1)<<3) + koffB;
#pragma unroll
    for(int s=0;s<nk;s++){ unsigned a[4],b[2];
        ldsm4(a,ap+s*16); ldsm2(b,bp+s*16);
        mmab(acc,a,b);}}

__global__ void __launch_bounds__(NTHR,1) ode_kernel(
        const float* __restrict__ ts,const float* __restrict__ yi,
        const float* __restrict__ w1,const float* __restrict__ b1,
        const float* __restrict__ w2,const float* __restrict__ b2,
        const float* __restrict__ w3,const float* __restrict__ b3,
        const float* __restrict__ Am,float* __restrict__ out){
    extern __shared__ float sm[];
    const int tid=threadIdx.x, wid=tid>>5, lane=tid&31;
    const int ws=wid>>3, wlocal=wid&7, lt=tid&255;
    const int gid=lane>>2, tig=lane&3;
    const int wn=(wlocal&3)*16, ks2=wlocal>>2;          // G1/G2: N4 x K2
    const int wn8=(wlocal&1)*8, ks4=wlocal>>1;          // G3: N2 x K4
    const int rank=blockIdx.x&7, clus=blockIdx.x>>3;
    const int m0w=clus*32+ws*16, n0h=rank*64, n0k=rank*16;
    const int bid=1+ws;

    __nv_bfloat16* w2h=(__nv_bfloat16*)(sm+O_W2H);
    __nv_bfloat16* w3h=(__nv_bfloat16*)(sm+O_W3H);
    __nv_bfloat16* ksm=(__nv_bfloat16*)(sm+O_KS+ws*5120);
    __nv_bfloat16* sg =(__nv_bfloat16*)(sm+O_SG+ws*4352);
    float* Zs=sm+O_Z+ws*2112;
    float* pt=sm+O_PT+ws*1088;
    const float* tss=sm+O_TS;
    const uint32_t ks_sma=sma(ksm);
    const uint32_t mb_h1=sma(sm+O_MB)+(ws*4+0)*8u;
    const uint32_t mb_h2=sma(sm+O_MB)+(ws*4+1)*8u;
    const uint32_t mb_k =sma(sm+O_MB)+(ws*4+2)*8u;
    const uint32_t mb_y =sma(sm+O_MB)+(ws*4+3)*8u;

    const int sr=lt>>4, sc=(lt&15)<<3;
    uint32_t sgb[4];
#pragma unroll
    for(int i=0;i<4;i++) sgb[i]=sma(sg+i*(16*136))+(uint32_t)(sr*136+sc)*2u;

    // ---- init (whole CTA) ----
    for(int i=tid;i<64*512;i+=NTHR){int n=i>>9,k=i&511;
        w2h[n*520+k]=__float2bfloat16(w2[(size_t)(n0h+n)*WW+k]);}
    for(int i=tid;i<16*512;i+=NTHR){int n=i>>9,k=i&511;
        w3h[n*520+k]=__float2bfloat16(w3[(size_t)(n0k+n)*WW+k]);}
    for(int i=tid;i<64*128;i+=NTHR){int n=i>>7,k=i&127;
        sm[O_W1+n*132+k]=f2tf32(w1[(size_t)(n0h+n)*DD+k]);}
    for(int i=tid;i<16*128;i+=NTHR){int n=i>>7,k=i&127;
        sm[O_AM+n*132+k]=f2tf32(Am[(size_t)(n0k+n)*DD+k]);}
    if(tid<64) sm[O_B+tid]=b1[n0h+tid];
    else if(tid<128) sm[O_B+tid]=b2[n0h+tid-64];
    else if(tid<144) sm[O_B+tid]=b3[n0k+tid-128];
    sm[O_TS+tid]=ts[tid];
    {   int i=rank*NTHR+tid;
        int r=i>>7,c=i&127; float v=yi[(size_t)(clus*32+r)*DD+c];
        __stcg(g_y+(size_t)(clus*32+r)*DD+c,v);
        out[(size_t)(clus*32+r)*TT*DD+c]=v;}
    if(tid==0){
#pragma unroll
        for(int i=0;i<8;i++) mbinit(sma(sm+O_MB)+i*8u,8);}
    __syncthreads();
    asm volatile("barrier.cluster.arrive.aligned;":::"memory");
    asm volatile("barrier.cluster.wait.aligned;":::"memory");

    const float* b1s=sm+O_B; const float* b2s=sm+O_B+64; const float* b3s=sm+O_B+128;
    unsigned ph_h1=0, ph_h2=0, ph_k=0, ph_y=0;
    const int zr=lt>>4, zc=(lt&15)<<3;
    const int cg=n0k+wn8+2*tig;
    const int r0g=m0w+gid;

    float yreg[8];

    for(int t=0;t<TT-1;t++){
        const float h=tss[t+1]-tss[t];
        float yacc[4]={0.f,0.f,0.f,0.f};
        if(t>0){ mbwait(mb_y,ph_y); ph_y^=1; }
        {   const float4* yp=(const float4*)(g_y+(size_t)(m0w+zr)*DD+zc);
            float4 a=__ldcg(yp), b=__ldcg(yp+1);
            yreg[0]=a.x;yreg[1]=a.y;yreg[2]=a.z;yreg[3]=a.w;
            yreg[4]=b.x;yreg[5]=b.y;yreg[6]=b.z;yreg[7]=b.w;}
        for(int s=0;s<6;s++){
            const int p=(t*6+s)&1;
            __nv_bfloat16* h1p=g_h1[p];
            __nv_bfloat16* h2p=g_h2[p];
            float ha[5];
#pragma unroll
            for(int j=0;j<5;j++) ha[j]=h*c_AT[s][j];
            if(s>0){ mbwait(mb_k,ph_k); ph_k^=1; }

            // ---- Z build ----
            {
                float z[8];
#pragma unroll
                for(int i=0;i<8;i++) z[i]=yreg[i];
                for(int j=0;j<s;j++){
                    float a=ha[j];
                    uint4 kk=*(const uint4*)(ksm + j*2048 + zr*128 + zc);
                    z[0]+=a*__uint_as_float(kk.x<<16);
                    z[1]+=a*__uint_as_float(kk.x&0xFFFF0000u);
                    z[2]+=a*__uint_as_float(kk.y<<16);
                    z[3]+=a*__uint_as_float(kk.y&0xFFFF0000u);
                    z[4]+=a*__uint_as_float(kk.z<<16);
                    z[5]+=a*__uint_as_float(kk.z&0xFFFF0000u);
                    z[6]+=a*__uint_as_float(kk.w<<16);
                    z[7]+=a*__uint_as_float(kk.w&0xFFFF0000u);}
                float* zd=Zs+zr*132+zc;
                *(float4*)zd    =make_float4(f2tf32(z[0]),f2tf32(z[1]),f2tf32(z[2]),f2tf32(z[3]));
                *(float4*)(zd+4)=make_float4(f2tf32(z[4]),f2tf32(z[5]),f2tf32(z[6]),f2tf32(z[7]));
            }
            nbar(bid);

            // ---- G1: H1 = tanh(Z @ w1^T + b1)  tf32 ----
            {
                float acc[2][4]={{0,0,0,0},{0,0,0,0}};
                mmaT16(Zs,132,sm+O_W1,132,acc,wn,ks2*64,lane);
                if(ks2==1){
                    int r0=gid, c=wn+2*tig;
                    *(float2*)(pt+r0*68+c)      =make_float2(acc[0][0],acc[0][1]);
                    *(float2*)(pt+(r0+8)*68+c)  =make_float2(acc[0][2],acc[0][3]);
                    *(float2*)(pt+r0*68+c+8)    =make_float2(acc[1][0],acc[1][1]);
                    *(float2*)(pt+(r0+8)*68+c+8)=make_float2(acc[1][2],acc[1][3]);}
                nbar(bid);
                if(ks2==0){
                    int r0=gid, c=wn+2*tig;
#pragma unroll
                    for(int j=0;j<2;j++){
                        float2 p0=*(float2*)(pt+r0*68+c+8*j);
                        float2 p1=*(float2*)(pt+(r0+8)*68+c+8*j);
                        float bb0=b1s[c+8*j], bb1=b1s[c+8*j+1];
                        int cgl=n0h+c+8*j;
                        unsigned u0=pack_bf2(ftanh(acc[j][0]+p0.x+bb0),ftanh(acc[j][1]+p0.y+bb1));
                        unsigned u1=pack_bf2(ftanh(acc[j][2]+p1.x+bb0),ftanh(acc[j][3]+p1.y+bb1));
                        __stcg((unsigned*)(h1p+(size_t)(m0w+r0)*WW+cgl),u0);
                        __stcg((unsigned*)(h1p+(size_t)(m0w+r0+8)*WW+cgl),u1);}}
                nbar(bid);
                if(wlocal==1&&lane==0){ fgpu();
#pragma unroll
                    for(unsigned rr=0;rr<8;rr++) mbarr_remote(mb_h1,rr);}
            }
            mbwait(mb_h1,ph_h1); ph_h1^=1;

            // ---- G2: H2 = tanh(H1 @ w2^T + b2)  bf16 ----
            {
#pragma unroll
                for(int ck=0;ck<4;ck++){
                    cpa(sgb[ck], h1p+(size_t)(m0w+sr)*WW+ck*128+sc); cpc();}
                float acc[2][4]={{0,0,0,0},{0,0,0,0}};
#pragma unroll
                for(int ck=0;ck<4;ck++){
                    if(ck==0)      asm volatile("cp.async.wait_group 3;":::"memory");
                    else if(ck==1) asm volatile("cp.async.wait_group 2;":::"memory");
                    else if(ck==2) asm volatile("cp.async.wait_group 1;":::"memory");
                    else           asm volatile("cp.async.wait_group 0;":::"memory");
                    nbar(bid);
                    mmaB16(sg+ck*(16*136),136,w2h,520,acc,wn,ks2*64,ck*128+ks2*64,lane,4);}
                nbar(bid);
                if(ks2==1){
                    int r0=gid, c=wn+2*tig;
                    *(float2*)(pt+r0*68+c)      =make_float2(acc[0][0],acc[0][1]);
                    *(float2*)(pt+(r0+8)*68+c)  =make_float2(acc[0][2],acc[0][3]);
                    *(float2*)(pt+r0*68+c+8)    =make_float2(acc[1][0],acc[1][1]);
                    *(float2*)(pt+(r0+8)*68+c+8)=make_float2(acc[1][2],acc[1][3]);}
                nbar(bid);
                if(ks2==0){
                    int r0=gid, c=wn+2*tig;
#pragma unroll
                    for(int j=0;j<2;j++){
                        float2 p0=*(float2*)(pt+r0*68+c+8*j);
                        float2 p1=*(float2*)(pt+(r0+8)*68+c+8*j);
                        float bb0=b2s[c+8*j], bb1=b2s[c+8*j+1];
                        int cgl=n0h+c+8*j;
                        unsigned u0=pack_bf2(ftanh(acc[j][0]+p0.x+bb0),ftanh(acc[j][1]+p0.y+bb1));
                        unsigned u1=pack_bf2(ftanh(acc[j][2]+p1.x+bb0),ftanh(acc[j][3]+p1.y+bb1));
                        __stcg((unsigned*)(h2p+(size_t)(m0w+r0)*WW+cgl),u0);
                        __stcg((unsigned*)(h2p+(size_t)(m0w+r0+8)*WW+cgl),u1);}}
                nbar(bid);
                if(wlocal==2&&lane==0){ fgpu();
#pragma unroll
                    for(unsigned rr=0;rr<8;rr++) mbarr_remote(mb_h2,rr);}
            }
            mbwait(mb_h2,ph_h2); ph_h2^=1;

            // ---- G3: k_s = H2 @ w3^T + b3 + Z @ A^T ----
            {
#pragma unroll
                for(int ck=0;ck<4;ck++){
                    cpa(sgb[ck], h2p+(size_t)(m0w+sr)*WW+ck*128+sc); cpc();}
                float acc3[4]={0,0,0,0};
                mmaT8(Zs,132,sm+O_AM,132,acc3,wn8,ks4*32,lane);
                float2 yo0,yo1;
                if(s==5 && ks4==0){
                    yo0=__ldcg((const float2*)(g_y+(size_t)r0g*DD+cg));
                    yo1=__ldcg((const float2*)(g_y+(size_t)(r0g+8)*DD+cg));}
#pragma unroll
                for(int ck=0;ck<4;ck++){
                    if(ck==0)      asm volatile("cp.async.wait_group 3;":::"memory");
                    else if(ck==1) asm volatile("cp.async.wait_group 2;":::"memory");
                    else if(ck==2) asm volatile("cp.async.wait_group 1;":::"memory");
                    else           asm volatile("cp.async.wait_group 0;":::"memory");
                    nbar(bid);
                    mmaB8(sg+ck*(16*136),136,w3h,520,acc3,wn8,ks4*32,ck*128+ks4*32,lane,2);}
                nbar(bid);
                if(ks4>0){
                    float* pr=pt+(ks4-1)*256;
                    int r0=gid, c=wn8+2*tig;
                    *(float2*)(pr+r0*16+c)    =make_float2(acc3[0],acc3[1]);
                    *(float2*)(pr+(r0+8)*16+c)=make_float2(acc3[2],acc3[3]);}
                nbar(bid);
                if(ks4==0){
                    int r0=gid, c=wn8+2*tig;
#pragma unroll
                    for(int q=0;q<3;q++){
                        float* pr=pt+q*256;
                        float2 q0=*(float2*)(pr+r0*16+c);
                        float2 q1=*(float2*)(pr+(r0+8)*16+c);
                        acc3[0]+=q0.x; acc3[1]+=q0.y; acc3[2]+=q1.x; acc3[3]+=q1.y;}
                    float bb0=b3s[cg-n0k], bb1=b3s[cg-n0k+1];
                    float kv[4];
                    kv[0]=acc3[0]+bb0; kv[1]=acc3[1]+bb1;
                    kv[2]=acc3[2]+bb0; kv[3]=acc3[3]+bb1;
                    if(s<5){
                        float bs=c_BT[s];
#pragma unroll
                        for(int i=0;i<4;i++) yacc[i]+=bs*kv[i];
#pragma unroll
                        for(int e=0;e<2;e++){
                            int lr=gid+e*8;
                            unsigned kp=pack_bf2(kv[2*e],kv[2*e+1]);
                            uint32_t la=ks_sma + (uint32_t)((s*2048)+lr*128+cg)*2u;
#pragma unroll
                            for(unsigned rr=0;rr<8;rr++) stclu(la,rr,kp);}
                    }else{
                        float b5=c_BT[5];
                        float y0=yo0.x+h*(yacc[0]+b5*kv[0]);
                        float y1=yo0.y+h*(yacc[1]+b5*kv[1]);
                        float y2=yo1.x+h*(yacc[2]+b5*kv[2]);
                        float y3=yo1.y+h*(yacc[3]+b5*kv[3]);
                        __stcg((float2*)(g_y+(size_t)r0g*DD+cg),make_float2(y0,y1));
                        __stcg((float2*)(g_y+(size_t)(r0g+8)*DD+cg),make_float2(y2,y3));
                        *(float2*)(out+(size_t)r0g*TT*DD+(size_t)(t+1)*DD+cg)
                            =make_float2(y0,y1);
                        *(float2*)(out+(size_t)(r0g+8)*TT*DD+(size_t)(t+1)*DD+cg)
                            =make_float2(y2,y3);}}
                nbar(bid);
                if(wlocal==3&&lane==0){ fgpu();
#pragma unroll
                    for(unsigned rr=0;rr<8;rr++) mbarr_remote(s<5?mb_k:mb_y,rr);}
            }
        }
    }
    // No CTA may exit while peers' remote SMEM stores/arrives are in flight.
    asm volatile("barrier.cluster.arrive.aligned;":::"memory");
    asm volatile("barrier.cluster.wait.aligned;":::"memory");
}

extern "C" void kernel_launch(void* const* d_in,const int* in_sizes,int n_in,
                              void* d_out,int out_size){
    (void)in_sizes;(void)n_in;(void)out_size;
    cudaFuncSetAttribute(ode_kernel,cudaFuncAttributeMaxDynamicSharedMemorySize,SMF*4);
    cudaLaunchConfig_t cfg={};
    cfg.gridDim=dim3(128,1,1);
    cfg.blockDim=dim3(NTHR,1,1);
    cfg.dynamicSmemBytes=SMF*4;
    cudaLaunchAttribute at[1];
    at[0].id=cudaLaunchAttributeClusterDimension;
    at[0].val.clusterDim.x=8; at[0].val.clusterDim.y=1; at[0].val.clusterDim.z=1;
    cfg.attrs=at; cfg.numAttrs=1;
    cudaLaunchKernelEx(&cfg,ode_kernel,
        (const float*)d_in[0],(const float*)d_in[1],(const float*)d_in[2],
        (const float*)d_in[3],(const float*)d_in[4],(const float*)d_in[5],
        (const float*)d_in[6],(const float*)d_in[7],(const float*)d_in[8],
        (float*)d_out);
}

// round 13
// speedup vs baseline: 1.2321x; 1.2321x over previous
#include <cuda_runtime.h>
#include <cuda_bf16.h>
#include <cstdint>

#define NB 512
#define DD 128
#define WW 512
#define TT 512
#define NTHR 512

// float-indexed SMEM layout
#define O_W1 0                       // 64x132 f32 (tf32)      8448
#define O_AM (O_W1+64*132)           // 16x132 f32             2112
#define O_B  (O_AM+16*132)           // 144 biases
#define O_TS (O_B+144)               // 512 ts
#define O_MB (O_TS+512)              // mbarriers (16 f)
#define O_Z  (O_MB+16)               // 32x132 f32             4224
#define O_KS (O_Z+4224)              // 5 x (32x128) bf16 = 10240 f
#define O_W2H (O_KS+10240)           // bf16 64x520 = 16640 f
#define O_W3H (O_W2H+16640)          // bf16 128x72 (K-slice) = 4608 f
#define O_H2S (O_W3H+4608)           // bf16 32x72 = 1152 f
#define O_PB  (O_H2S+1152)           // partials 8x32x16 f32 = 4096 f
#define O_SG  (O_PB+4096)            // 2 x (32x136) bf16 = 4352 f ; pt aliases buf0
#define SMF   (O_SG+4352)            // 56544 f = 226176 B

__device__ __align__(16) __nv_bfloat16 g_h1[NB*WW];
__device__ __align__(16) float g_y[NB*DD];

__constant__ float c_AT[6][5] = {
    {0.f,0.f,0.f,0.f,0.f},
    {0.161f,0.f,0.f,0.f,0.f},
    {-0.008480655492356989f,0.335480655492357f,0.f,0.f,0.f},
    {2.8971530571054935f,-6.359448489975075f,4.3622954328695815f,0.f,0.f},
    {5.325864828439257f,-11.748883564062828f,7.4955393428898365f,-0.09249506636175525f,0.f},
    {5.86145544294642f,-12.92096931784711f,8.159367898576159f,-0.071584973281401f,-0.028269050394068383f}};
__constant__ float c_BT[6] = {0.09646076681806523f,0.01f,0.4798896504144996f,
                              1.379008574103742f,-3.290069515436081f,2.324710524099774f};

__device__ __forceinline__ float f2tf32(float x){
    unsigned u; asm("cvt.rna.tf32.f32 %0,%1;":"=r"(u):"f"(x)); return __uint_as_float(u);}
__device__ __forceinline__ float ftanh(float x){
    float e = exp2f(2.885390081777927f * x);
    return 1.0f - __fdividef(2.0f, e + 1.0f);}
__device__ __forceinline__ unsigned pack_bf2(float lo,float hi){
    unsigned r; asm("cvt.rn.bf16x2.f32 %0,%1,%2;":"=r"(r):"f"(hi),"f"(lo)); return r;}
__device__ __forceinline__ void mma8(float* c,const unsigned* a,const unsigned* b){
    asm volatile("mma.sync.aligned.m16n8k8.row.col.f32.tf32.tf32.f32 "
        "{%0,%1,%2,%3},{%4,%5,%6,%7},{%8,%9},{%0,%1,%2,%3};"
        :"+f"(c[0]),"+f"(c[1]),"+f"(c[2]),"+f"(c[3])
        :"r"(a[0]),"r"(a[1]),"r"(a[2]),"r"(a[3]),"r"(b[0]),"r"(b[1]));}
__device__ __forceinline__ void mmab(float* c,const unsigned* a,const unsigned* b){
    asm volatile("mma.sync.aligned.m16n8k16.row.col.f32.bf16.bf16.f32 "
        "{%0,%1,%2,%3},{%4,%5,%6,%7},{%8,%9},{%0,%1,%2,%3};"
        :"+f"(c[0]),"+f"(c[1]),"+f"(c[2]),"+f"(c[3])
        :"r"(a[0]),"r"(a[1]),"r"(a[2]),"r"(a[3]),"r"(b[0]),"r"(b[1]));}
__device__ __forceinline__ unsigned sma(const void* p){
    return (unsigned)__cvta_generic_to_shared(p);}
__device__ __forceinline__ void ldsm4(unsigned r[4], const void* p){
    asm volatile("ldmatrix.sync.aligned.m8n8.x4.shared.b16 {%0,%1,%2,%3},[%4];"
        :"=r"(r[0]),"=r"(r[1]),"=r"(r[2]),"=r"(r[3]):"r"(sma(p)));}
__device__ __forceinline__ void ldsm2(unsigned r[2], const void* p){
    asm volatile("ldmatrix.sync.aligned.m8n8.x2.shared.b16 {%0,%1},[%2];"
        :"=r"(r[0]),"=r"(r[1]):"r"(sma(p)));}
__device__ __forceinline__ void cpa(uint32_t d,const void* s){
    asm volatile("cp.async.cg.shared.global [%0],[%1],16;"::"r"(d),"l"(s):"memory");}
__device__ __forceinline__ void cpc(){asm volatile("cp.async.commit_group;":::"memory");}
__device__ __forceinline__ void cbar(){
    asm volatile("barrier.cluster.arrive.aligned;":::"memory");
    asm volatile("barrier.cluster.wait.aligned;":::"memory");}
__device__ __forceinline__ void fgpu(){
    asm volatile("fence.acq_rel.gpu;":::"memory");}
__device__ __forceinline__ void mbinit(uint32_t a,unsigned c){
    asm volatile("mbarrier.init.shared.b64 [%0],%1;"::"r"(a),"r"(c):"memory");}
__device__ __forceinline__ void mbarr_remote(uint32_t la,unsigned rr){
    uint32_t ra;
    asm volatile("mapa.shared::cluster.u32 %0,%1,%2;":"=r"(ra):"r"(la),"r"(rr));
    asm volatile("mbarrier.arrive.release.cluster.shared::cluster.b64 _,[%0];"
                 ::"r"(ra):"memory");}
__device__ __forceinline__ void mbwait(uint32_t a,unsigned ph){
    unsigned done;
    do{ asm volatile("{\n\t.reg .pred p;\n\t"
        "mbarrier.try_wait.parity.acquire.cluster.shared::cta.b64 p,[%1],%2,0x989680;\n\t"
        "selp.b32 %0,1,0,p;\n\t}":"=r"(done):"r"(a),"r"(ph):"memory");
    }while(!done);}
__device__ __forceinline__ void stclu(uint32_t laddr,unsigned rr,unsigned v){
    uint32_t ra;
    asm volatile("mapa.shared::cluster.u32 %0,%1,%2;":"=r"(ra):"r"(laddr),"r"(rr));
    asm volatile("st.shared::cluster.u32 [%0],%1;"::"r"(ra),"r"(v):"memory");}
__device__ __forceinline__ void stclu64(uint32_t laddr,unsigned rr,float2 v){
    uint32_t ra;
    unsigned long long u=*(unsigned long long*)&v;
    asm volatile("mapa.shared::cluster.u32 %0,%1,%2;":"=r"(ra):"r"(laddr),"r"(rr));
    asm volatile("st.shared::cluster.b64 [%0],%1;"::"r"(ra),"l"(u):"memory");}

// tf32 m16n16, 64 K-cols from koff
__device__ __forceinline__ void mmaT16(const float* A,int lda,const float* B,int ldb,
        float acc[2][4],int wm,int wn,int koff,int lane){
    const float* ap = A + (wm+(lane&15))*lda + ((lane>>4)<<2) + koff;
    const float* bp = B + (wn+(lane&7)+((lane>>4)<<3))*ldb + (((lane>>3)&1)<<2) + koff;
#pragma unroll
    for(int kk=0;kk<64;kk+=8){ unsigned a[4],b[4];
        ldsm4(a,ap+kk); ldsm4(b,bp+kk);
        mma8(acc[0],a,b); mma8(acc[1],a,b+2);}}

// tf32 m16n8, 32 K-cols from koff
__device__ __forceinline__ void mmaT8(const float* A,int lda,const float* B,int ldb,
        float acc[4],int wm,int wn8,int koff,int lane){
    const float* ap = A + (wm+(lane&15))*lda + ((lane>>4)<<2) + koff;
    const float* bp = B + (wn8+(lane&7))*ldb + (((lane>>3)&1)<<2) + koff;
#pragma unroll
    for(int kk=0;kk<32;kk+=8){ unsigned a[4],b[2];
        ldsm4(a,ap+kk); ldsm2(b,bp+kk);
        mma8(acc,a,b);}}

// bf16 m16n16, nk k16-steps
__device__ __forceinline__ void mmaB16(const __nv_bfloat16* A,int lda,
        const __nv_bfloat16* B,int ldb,float acc[2][4],int wm,int wn,
        int koffA,int koffB,int lane,int nk){
    const __nv_bfloat16* ap = A + (wm+(lane&15))*lda + ((lane>>4)<<3) + koffA;
    const __nv_bfloat16* bp = B + (wn+(lane&7)+((lane>>4)<<3))*ldb + (((lane>>3)&1)<<3) + koffB;
#pragma unroll
    for(int s=0;s<nk;s++){ unsigned a[4],b[4];
        ldsm4(a,ap+s*16); ldsm4(b,bp+s*16);
        mmab(acc[0],a,b); mmab(acc[1],a,b+2);}}

// bf16 m16n8, nk k16-steps
__device__ __forceinline__ void mmaB8(const __nv_bfloat16* A,int lda,
        const __nv_bfloat16* B,int ldb,float acc[4],int wm,int wn8,
        int koffA,int koffB,int lane,int nk){
    const __nv_bfloat16* ap = A + (wm+(lane&15))*lda + ((lane>>4)<<3) + koffA;
    const __nv_bfloat16* bp = B + (wn8+(lane&7))*ldb + (((lane>>3)&1)<<3) + koffB;
#pragma unroll
    for(int s=0;s<nk;s++){ unsigned a[4],b[2];
        ldsm4(a,ap+s*16); ldsm2(b,bp+s*16);
        mmab(acc,a,b);}}

__global__ void __launch_bounds__(NTHR,1) ode_kernel(
        const float* __restrict__ ts,const float* __restrict__ yi,
        const float* __restrict__ w1,const float* __restrict__ b1,
        const float* __restrict__ w2,const float* __restrict__ b2,
        const float* __restrict__ w3,const float* __restrict__ b3,
        const float* __restrict__ Am,float* __restrict__ out){
    extern __shared__ float sm[];
    const int tid=threadIdx.x, wid=tid>>5, lane=tid&31;
    const int gid=lane>>2, tig=lane&3;
    const int wm=(wid&1)*16, wn=((wid>>1)&3)*16, ks2=wid>>3;   // G1/G2: 2M x 4N x 2K
    const int wmP=(wid&1)*16, wnP=(wid>>1)*8;                  // G3 partial: 2M x 8N(n8) x2tiles
    const int wnz=((wid>>1)&1)*8;                              // reduction warps 0-3
    const int rank=blockIdx.x&7, clus=blockIdx.x>>3;
    const int m0=clus*32, n0h=rank*64, n0k=rank*16;

    __nv_bfloat16* w2h=(__nv_bfloat16*)(sm+O_W2H);
    __nv_bfloat16* w3h=(__nv_bfloat16*)(sm+O_W3H);
    __nv_bfloat16* h2s=(__nv_bfloat16*)(sm+O_H2S);
    __nv_bfloat16* ksm=(__nv_bfloat16*)(sm+O_KS);
    __nv_bfloat16* sg =(__nv_bfloat16*)(sm+O_SG);
    float* Zs=sm+O_Z;
    float* pbuf=sm+O_PB;
    float* pt=sm+O_SG;                  // alias staging buf0 (disjoint lifetime)
    const float* tss=sm+O_TS;
    const uint32_t ks_sma=sma(ksm);
    const uint32_t pb_sma=sma(pbuf);
    const uint32_t mb_p=sma(sm+O_MB)+0u;
    const uint32_t mb_k=sma(sm+O_MB)+8u;
    const uint32_t mb_y=sma(sm+O_MB)+16u;

    const int sr=tid>>4, sc=(tid&15)<<3;
    uint32_t sgb[2];
#pragma unroll
    for(int i=0;i<2;i++) sgb[i]=sma(sg+i*(32*136))+(uint32_t)(sr*136+sc)*2u;

    // ---- init ----
    for(int i=tid;i<64*512;i+=NTHR){int n=i>>9,k=i&511;
        w2h[n*520+k]=__float2bfloat16(w2[(size_t)(n0h+n)*WW+k]);}
    for(int i=tid;i<128*64;i+=NTHR){int d=i>>6,kk=i&63;      // K-slice of w3: cols n0h..+64
        w3h[d*72+kk]=__float2bfloat16(w3[(size_t)d*WW+n0h+kk]);}
    for(int i=tid;i<64*128;i+=NTHR){int n=i>>7,k=i&127;
        sm[O_W1+n*132+k]=f2tf32(w1[(size_t)(n0h+n)*DD+k]);}
    for(int i=tid;i<16*128;i+=NTHR){int n=i>>7,k=i&127;
        sm[O_AM+n*132+k]=f2tf32(Am[(size_t)(n0k+n)*DD+k]);}
    if(tid<64) sm[O_B+tid]=b1[n0h+tid];
    else if(tid<128) sm[O_B+tid]=b2[n0h+tid-64];
    else if(tid<144) sm[O_B+tid]=b3[n0k+tid-128];
    sm[O_TS+tid]=ts[tid];
    {   int i=rank*NTHR+tid;
        int r=i>>7,c=i&127; float v=yi[(size_t)(m0+r)*DD+c];
        __stcg(g_y+(size_t)(m0+r)*DD+c,v);
        out[(size_t)(m0+r)*TT*DD+c]=v;}
    if(tid==0){ mbinit(mb_p,8); mbinit(mb_k,8); mbinit(mb_y,8); }
    __syncthreads();
    cbar();

    const float* b1s=sm+O_B; const float* b2s=sm+O_B+64; const float* b3s=sm+O_B+128;
    unsigned ph_p=0, ph_k=0, ph_y=0;
    const int zr=tid>>4, zc=(tid&15)<<3;
    const int lcr=wnz+2*tig;            // reduction local col (warps 0-3)
    const int cg=n0k+lcr;               // global col
    const int r0g=m0+wm+gid;

    float yreg[8];
    float yacc[4]={0.f,0.f,0.f,0.f};

    for(int t=0;t<TT-1;t++){
        const float h=tss[t+1]-tss[t];
        if(t>0){ mbwait(mb_y,ph_y); ph_y^=1; }
        {   const float4* yp=(const float4*)(g_y+(size_t)(m0+zr)*DD+zc);
            float4 a=__ldcg(yp), b=__ldcg(yp+1);
            yreg[0]=a.x;yreg[1]=a.y;yreg[2]=a.z;yreg[3]=a.w;
            yreg[4]=b.x;yreg[5]=b.y;yreg[6]=b.z;yreg[7]=b.w;}
        if(wid<4){ yacc[0]=yacc[1]=yacc[2]=yacc[3]=0.f; }
        for(int s=0;s<6;s++){
            float ha[5];
#pragma unroll
            for(int j=0;j<5;j++) ha[j]=h*c_AT[s][j];
            if(s>0){ mbwait(mb_k,ph_k); ph_k^=1; }

            // ---- Z build: y(regs) + sum ha_j*k_j (bf16 SMEM) -> tf32 ----
            {
                float z[8];
#pragma unroll
                for(int i=0;i<8;i++) z[i]=yreg[i];
                for(int j=0;j<s;j++){
                    float a=ha[j];
                    uint4 kk=*(const uint4*)(ksm + j*4096 + zr*128 + zc);
                    z[0]+=a*__uint_as_float(kk.x<<16);
                    z[1]+=a*__uint_as_float(kk.x&0xFFFF0000u);
                    z[2]+=a*__uint_as_float(kk.y<<16);
                    z[3]+=a*__uint_as_float(kk.y&0xFFFF0000u);
                    z[4]+=a*__uint_as_float(kk.z<<16);
                    z[5]+=a*__uint_as_float(kk.z&0xFFFF0000u);
                    z[6]+=a*__uint_as_float(kk.w<<16);
                    z[7]+=a*__uint_as_float(kk.w&0xFFFF0000u);}
                float* zd=Zs+zr*132+zc;
                *(float4*)zd    =make_float4(f2tf32(z[0]),f2tf32(z[1]),f2tf32(z[2]),f2tf32(z[3]));
                *(float4*)(zd+4)=make_float4(f2tf32(z[4]),f2tf32(z[5]),f2tf32(z[6]),f2tf32(z[7]));
            }
            __syncthreads();

            // ---- G1: H1 = tanh(Z @ w1^T + b1)  tf32 -> g_h1 (gmem, for peers) ----
            {
                float acc[2][4]={{0,0,0,0},{0,0,0,0}};
                mmaT16(Zs,132,sm+O_W1,132,acc,wm,wn,ks2*64,lane);
                if(ks2==1){
                    int r0=wm+gid, c=wn+2*tig;
                    *(float2*)(pt+r0*68+c)      =make_float2(acc[0][0],acc[0][1]);
                    *(float2*)(pt+(r0+8)*68+c)  =make_float2(acc[0][2],acc[0][3]);
                    *(float2*)(pt+r0*68+c+8)    =make_float2(acc[1][0],acc[1][1]);
                    *(float2*)(pt+(r0+8)*68+c+8)=make_float2(acc[1][2],acc[1][3]);}
                __syncthreads();
                if(ks2==0){
                    int r0=wm+gid, c=wn+2*tig;
#pragma unroll
                    for(int j=0;j<2;j++){
                        float2 p0=*(float2*)(pt+r0*68+c+8*j);
                        float2 p1=*(float2*)(pt+(r0+8)*68+c+8*j);
                        float bb0=b1s[c+8*j], bb1=b1s[c+8*j+1];
                        int cgl=n0h+c+8*j;
                        unsigned u0=pack_bf2(ftanh(acc[0+j][0]+p0.x+bb0),ftanh(acc[j][1]+p0.y+bb1));
                        unsigned u1=pack_bf2(ftanh(acc[j][2]+p1.x+bb0),ftanh(acc[j][3]+p1.y+bb1));
                        __stcg((unsigned*)(g_h1+(size_t)(m0+r0)*WW+cgl),u0);
                        __stcg((unsigned*)(g_h1+(size_t)(m0+r0+8)*WW+cgl),u1);}}
            }
            cbar();   // H1 exchange (the only full-cluster rendezvous per stage)

            // ---- G2: H2 = tanh(H1 @ w2^T + b2)  bf16, 2-buffer pipeline -> h2s SMEM ----
            {
                cpa(sgb[0], g_h1+(size_t)(m0+sr)*WW+0*128+sc); cpc();
                cpa(sgb[1], g_h1+(size_t)(m0+sr)*WW+1*128+sc); cpc();
                float acc[2][4]={{0,0,0,0},{0,0,0,0}};
#pragma unroll
                for(int ck=0;ck<4;ck++){
                    if(ck<3) asm volatile("cp.async.wait_group 1;":::"memory");
                    else     asm volatile("cp.async.wait_group 0;":::"memory");
                    __syncthreads();
                    mmaB16(sg+(ck&1)*(32*136),136,w2h,520,acc,wm,wn,ks2*64,ck*128+ks2*64,lane,4);
                    if(ck<2){
                        __syncthreads();
                        cpa(sgb[ck&1], g_h1+(size_t)(m0+sr)*WW+(ck+2)*128+sc); cpc();}
                }
                __syncthreads();
                if(ks2==1){
                    int r0=wm+gid, c=wn+2*tig;
                    *(float2*)(pt+r0*68+c)      =make_float2(acc[0][0],acc[0][1]);
                    *(float2*)(pt+(r0+8)*68+c)  =make_float2(acc[0][2],acc[0][3]);
                    *(float2*)(pt+r0*68+c+8)    =make_float2(acc[1][0],acc[1][1]);
                    *(float2*)(pt+(r0+8)*68+c+8)=make_float2(acc[1][2],acc[1][3]);}
                __syncthreads();
                if(ks2==0){
                    int r0=wm+gid, c=wn+2*tig;
#pragma unroll
                    for(int j=0;j<2;j++){
                        float2 p0=*(float2*)(pt+r0*68+c+8*j);
                        float2 p1=*(float2*)(pt+(r0+8)*68+c+8*j);
                        float bb0=b2s[c+8*j], bb1=b2s[c+8*j+1];
                        int cl=c+8*j;
                        unsigned u0=pack_bf2(ftanh(acc[j][0]+p0.x+bb0),ftanh(acc[j][1]+p0.y+bb1));
                        unsigned u1=pack_bf2(ftanh(acc[j][2]+p1.x+bb0),ftanh(acc[j][3]+p1.y+bb1));
                        *(unsigned*)(h2s+r0*72+cl)    =u0;
                        *(unsigned*)(h2s+(r0+8)*72+cl)=u1;}}
            }
            __syncthreads();   // h2s ready (local only — NO cluster sync!)

            // ---- G3a: partial P = H2_own @ w3_slice^T (N=128, K=64, all local) ----
            {
                float aP0[4]={0,0,0,0}, aP1[4]={0,0,0,0};
                mmaB8(h2s,72,w3h,72,aP0,wmP,wnP,0,0,lane,4);
                mmaB8(h2s,72,w3h,72,aP1,wmP,wnP+64,0,0,lane,4);
                // push slices to owner CTAs' pbuf[my_rank]
#pragma unroll
                for(int j=0;j<2;j++){
                    float* aP=j?aP1:aP0;
                    int cglob=wnP+j*64+2*tig;
                    unsigned d=(unsigned)(cglob>>4); int lc=cglob&15;
#pragma unroll
                    for(int e=0;e<2;e++){
                        int row=wmP+gid+e*8;
                        float2 v=make_float2(aP[2*e],aP[2*e+1]);
                        uint32_t la=pb_sma+(uint32_t)((rank*32+row)*16+lc)*4u;
                        stclu64(la,d,v);}}
            }
            __syncthreads();
            if(wid==8&&lane==0){ fgpu();
#pragma unroll
                for(unsigned rr=0;rr<8;rr++) mbarr_remote(mb_p,rr);}

            // ---- G3b: reduction warps 0-3: Z@A^T + sum partials + b3 -> k slice ----
            if(wid<4){
                float acc3[4]={0,0,0,0};
#pragma unroll
                for(int ko=0;ko<128;ko+=32)
                    mmaT8(Zs,132,sm+O_AM,132,acc3,wm,wnz,ko,lane);
                float2 yo0,yo1;
                if(s==5){
                    yo0=__ldcg((const float2*)(g_y+(size_t)r0g*DD+cg));
                    yo1=__ldcg((const float2*)(g_y+(size_t)(r0g+8)*DD+cg));}
                mbwait(mb_p,ph_p); ph_p^=1;
                int row0=wm+gid;
#pragma unroll
                for(int src=0;src<8;src++){
                    float2 q0=*(float2*)(pbuf+(src*32+row0)*16+lcr);
                    float2 q1=*(float2*)(pbuf+(src*32+row0+8)*16+lcr);
                    acc3[0]+=q0.x; acc3[1]+=q0.y; acc3[2]+=q1.x; acc3[3]+=q1.y;}
                float bb0=b3s[lcr], bb1=b3s[lcr+1];
                float kv[4];
                kv[0]=acc3[0]+bb0; kv[1]=acc3[1]+bb1;
                kv[2]=acc3[2]+bb0; kv[3]=acc3[3]+bb1;
                if(s<5){
                    float bs=c_BT[s];
#pragma unroll
                    for(int i=0;i<4;i++) yacc[i]+=bs*kv[i];
#pragma unroll
                    for(int e=0;e<2;e++){
                        int lr=wm+gid+e*8;
                        unsigned kp=pack_bf2(kv[2*e],kv[2*e+1]);
                        uint32_t la=ks_sma+(uint32_t)((s<<12)+lr*128+cg)*2u;
#pragma unroll
                        for(unsigned rr=0;rr<8;rr++) stclu(la,rr,kp);}
                    asm volatile("bar.sync 1,128;":::"memory");
                    if(tid==0){ fgpu();
#pragma unroll
                        for(unsigned rr=0;rr<8;rr++) mbarr_remote(mb_k,rr);}
                }else{
                    float b5=c_BT[5];
                    float y0=yo0.x+h*(yacc[0]+b5*kv[0]);
                    float y1=yo0.y+h*(yacc[1]+b5*kv[1]);
                    float y2=yo1.x+h*(yacc[2]+b5*kv[2]);
                    float y3=yo1.y+h*(yacc[3]+b5*kv[3]);
                    __stcg((float2*)(g_y+(size_t)r0g*DD+cg),make_float2(y0,y1));
                    __stcg((float2*)(g_y+(size_t)(r0g+8)*DD+cg),make_float2(y2,y3));
                    *(float2*)(out+(size_t)r0g*TT*DD+(size_t)(t+1)*DD+cg)
                        =make_float2(y0,y1);
                    *(float2*)(out+(size_t)(r0g+8)*TT*DD+(size_t)(t+1)*DD+cg)
                        =make_float2(y2,y3);
                    asm volatile("bar.sync 1,128;":::"memory");
                    if(tid==0){ fgpu();
#pragma unroll
                        for(unsigned rr=0;rr<8;rr++) mbarr_remote(mb_y,rr);}
                }
            }
            // warps 4-15 proceed directly to next stage (gated by mb_k / mb_y)
        }
    }
    // No CTA may exit while peers' remote SMEM stores/arrives are in flight.
    cbar();
}

extern "C" void kernel_launch(void* const* d_in,const int* in_sizes,int n_in,
                              void* d_out,int out_size){
    (void)in_sizes;(void)n_in;(void)out_size;
    cudaFuncSetAttribute(ode_kernel,cudaFuncAttributeMaxDynamicSharedMemorySize,SMF*4);
    cudaLaunchConfig_t cfg={};
    cfg.gridDim=dim3(128,1,1);
    cfg.blockDim=dim3(NTHR,1,1);
    cfg.dynamicSmemBytes=SMF*4;
    cudaLaunchAttribute at[1];
    at[0].id=cudaLaunchAttributeClusterDimension;
    at[0].val.clusterDim.x=8; at[0].val.clusterDim.y=1; at[0].val.clusterDim.z=1;
    cfg.attrs=at; cfg.numAttrs=1;
    cudaLaunchKernelEx(&cfg,ode_kernel,
        (const float*)d_in[0],(const float*)d_in[1],(const float*)d_in[2],
        (const float*)d_in[3],(const float*)d_in[4],(const float*)d_in[5],
        (const float*)d_in[6],(const float*)d_in[7],(const float*)d_in[8],
        (float*)d_out);
}

// round 14
// speedup vs baseline: 1.4010x; 1.1371x over previous
#include <cuda_runtime.h>
#include <cuda_bf16.h>
#include <cstdint>

#define NB 512
#define DD 128
#define WW 512
#define TT 512
#define NTHR 512

// float-indexed SMEM layout
#define O_W1 0                         // 64x132 f32 (tf32)      8448
#define O_AM (O_W1+64*132)             // 16x132 f32             2112
#define O_Z  (O_AM+16*132)             // 32x132 f32             4224
#define O_B  (O_Z+4224)                // 144 biases
#define O_TS (O_B+144)                 // 512 ts
#define O_MB (O_TS+512)                // 2 mbarriers -> 16 f
#define O_KS (O_MB+16)                 // 5 x (32x128) bf16 = 10240 f
#define O_W2H (O_KS+10240)             // bf16 64x520 = 16640 f
#define O_W3H (O_W2H+16640)            // bf16 16x520 = 4160 f
#define O_SG  (O_W3H+4160)             // 4 x (32x136) bf16 = 8704 f; pt aliases sg[3]
#define SGF   2176
#define SMF   (O_SG+8704)              // 55200 f = 220800 B

__device__ __align__(16) __nv_bfloat16 g_h1[NB*WW];
__device__ __align__(16) __nv_bfloat16 g_h2[NB*WW];
__device__ __align__(16) float g_y[NB*DD];

__constant__ float c_AT[6][5] = {
    {0.f,0.f,0.f,0.f,0.f},
    {0.161f,0.f,0.f,0.f,0.f},
    {-0.008480655492356989f,0.335480655492357f,0.f,0.f,0.f},
    {2.8971530571054935f,-6.359448489975075f,4.3622954328695815f,0.f,0.f},
    {5.325864828439257f,-11.748883564062828f,7.4955393428898365f,-0.09249506636175525f,0.f},
    {5.86145544294642f,-12.92096931784711f,8.159367898576159f,-0.071584973281401f,-0.028269050394068383f}};
__constant__ float c_BT[6] = {0.09646076681806523f,0.01f,0.4798896504144996f,
                              1.379008574103742f,-3.290069515436081f,2.324710524099774f};

__device__ __forceinline__ float f2tf32(float x){
    unsigned u; asm("cvt.rna.tf32.f32 %0,%1;":"=r"(u):"f"(x)); return __uint_as_float(u);}
__device__ __forceinline__ float ftanh(float x){
    float e = exp2f(2.885390081777927f * x);
    return 1.0f - __fdividef(2.0f, e + 1.0f);}
__device__ __forceinline__ unsigned pack_bf2(float lo,float hi){
    unsigned r; asm("cvt.rn.bf16x2.f32 %0,%1,%2;":"=r"(r):"f"(hi),"f"(lo)); return r;}
__device__ __forceinline__ void mma8(float* c,const unsigned* a,const unsigned* b){
    asm volatile("mma.sync.aligned.m16n8k8.row.col.f32.tf32.tf32.f32 "
        "{%0,%1,%2,%3},{%4,%5,%6,%7},{%8,%9},{%0,%1,%2,%3};"
        :"+f"(c[0]),"+f"(c[1]),"+f"(c[2]),"+f"(c[3])
        :"r"(a[0]),"r"(a[1]),"r"(a[2]),"r"(a[3]),"r"(b[0]),"r"(b[1]));}
__device__ __forceinline__ void mmab(float* c,const unsigned* a,const unsigned* b){
    asm volatile("mma.sync.aligned.m16n8k16.row.col.f32.bf16.bf16.f32 "
        "{%0,%1,%2,%3},{%4,%5,%6,%7},{%8,%9},{%0,%1,%2,%3};"
        :"+f"(c[0]),"+f"(c[1]),"+f"(c[2]),"+f"(c[3])
        :"r"(a[0]),"r"(a[1]),"r"(a[2]),"r"(a[3]),"r"(b[0]),"r"(b[1]));}
__device__ __forceinline__ unsigned sma(const void* p){
    return (unsigned)__cvta_generic_to_shared(p);}
__device__ __forceinline__ void ldsm4(unsigned r[4], const void* p){
    asm volatile("ldmatrix.sync.aligned.m8n8.x4.shared.b16 {%0,%1,%2,%3},[%4];"
        :"=r"(r[0]),"=r"(r[1]),"=r"(r[2]),"=r"(r[3]):"r"(sma(p)));}
__device__ __forceinline__ void ldsm2(unsigned r[2], const void* p){
    asm volatile("ldmatrix.sync.aligned.m8n8.x2.shared.b16 {%0,%1},[%2];"
        :"=r"(r[0]),"=r"(r[1]):"r"(sma(p)));}
__device__ __forceinline__ void cpa(uint32_t d,const void* s){
    asm volatile("cp.async.cg.shared.global [%0],[%1],16;"::"r"(d),"l"(s):"memory");}
__device__ __forceinline__ void cpc(){asm volatile("cp.async.commit_group;":::"memory");}
__device__ __forceinline__ void carr(){
    asm volatile("barrier.cluster.arrive.aligned;":::"memory");}
__device__ __forceinline__ void cwait(){
    asm volatile("barrier.cluster.wait.aligned;":::"memory");}
__device__ __forceinline__ void fgpu(){
    asm volatile("fence.acq_rel.gpu;":::"memory");}
__device__ __forceinline__ void mbinit(uint32_t a,unsigned c){
    asm volatile("mbarrier.init.shared.b64 [%0],%1;"::"r"(a),"r"(c):"memory");}
__device__ __forceinline__ void mbarr_remote(uint32_t la,unsigned rr){
    uint32_t ra;
    asm volatile("mapa.shared::cluster.u32 %0,%1,%2;":"=r"(ra):"r"(la),"r"(rr));
    asm volatile("mbarrier.arrive.release.cluster.shared::cluster.b64 _,[%0];"
                 ::"r"(ra):"memory");}
__device__ __forceinline__ void mbwait(uint32_t a,unsigned ph){
    unsigned done;
    do{ asm volatile("{\n\t.reg .pred p;\n\t"
        "mbarrier.try_wait.parity.acquire.cluster.shared::cta.b64 p,[%1],%2,0x989680;\n\t"
        "selp.b32 %0,1,0,p;\n\t}":"=r"(done):"r"(a),"r"(ph):"memory");
    }while(!done);}
__device__ __forceinline__ void stclu(uint32_t laddr,unsigned rr,unsigned v){
    uint32_t ra;
    asm volatile("mapa.shared::cluster.u32 %0,%1,%2;":"=r"(ra):"r"(laddr),"r"(rr));
    asm volatile("st.shared::cluster.u32 [%0],%1;"::"r"(ra),"r"(v):"memory");}

// tf32 m16n16, 64 K-cols from koff
__device__ __forceinline__ void mmaT16(const float* A,int lda,const float* B,int ldb,
        float acc[2][4],int wm,int wn,int koff,int lane){
    const float* ap = A + (wm+(lane&15))*lda + ((lane>>4)<<2) + koff;
    const float* bp = B + (wn+(lane&7)+((lane>>4)<<3))*ldb + (((lane>>3)&1)<<2) + koff;
#pragma unroll
    for(int kk=0;kk<64;kk+=8){ unsigned a[4],b[4];
        ldsm4(a,ap+kk); ldsm4(b,bp+kk);
        mma8(acc[0],a,b); mma8(acc[1],a,b+2);}}

// tf32 m16n8, 32 K-cols from koff
__device__ __forceinline__ void mmaT8(const float* A,int lda,const float* B,int ldb,
        float acc[4],int wm,int wn8,int koff,int lane){
    const float* ap = A + (wm+(lane&15))*lda + ((lane>>4)<<2) + koff;
    const float* bp = B + (wn8+(lane&7))*ldb + (((lane>>3)&1)<<2) + koff;
#pragma unroll
    for(int kk=0;kk<32;kk+=8){ unsigned a[4],b[2];
        ldsm4(a,ap+kk); ldsm2(b,bp+kk);
        mma8(acc,a,b);}}

// bf16 m16n16, nk k16-steps
__device__ __forceinline__ void mmaB16(const __nv_bfloat16* A,int lda,
        const __nv_bfloat16* B,int ldb,float acc[2][4],int wm,int wn,
        int koffA,int koffB,int lane,int nk){
    const __nv_bfloat16* ap = A + (wm+(lane&15))*lda + ((lane>>4)<<3) + koffA;
    const __nv_bfloat16* bp = B + (wn+(lane&7)+((lane>>4)<<3))*ldb + (((lane>>3)&1)<<3) + koffB;
#pragma unroll
    for(int s=0;s<nk;s++){ unsigned a[4],b[4];
        ldsm4(a,ap+s*16); ldsm4(b,bp+s*16);
        mmab(acc[0],a,b); mmab(acc[1],a,b+2);}}

// bf16 m16n8, nk k16-steps
__device__ __forceinline__ void mmaB8(const __nv_bfloat16* A,int lda,
        const __nv_bfloat16* B,int ldb,float acc[4],int wm,int wn8,
        int koffA,int koffB,int lane,int nk){
    const __nv_bfloat16* ap = A + (wm+(lane&15))*lda + ((lane>>4)<<3) + koffA;
    const __nv_bfloat16* bp = B + (wn8+(lane&7))*ldb + (((lane>>3)&1)<<3) + koffB;
#pragma unroll
    for(int s=0;s<nk;s++){ unsigned a[4],b[2];
        ldsm4(a,ap+s*16); ldsm2(b,bp+s*16);
        mmab(acc,a,b);}}

__global__ void __launch_bounds__(NTHR,1) ode_kernel(
        const float* __restrict__ ts,const float* __restrict__ yi,
        const float* __restrict__ w1,const float* __restrict__ b1,
        const float* __restrict__ w2,const float* __restrict__ b2,
        const float* __restrict__ w3,const float* __restrict__ b3,
        const float* __restrict__ Am,float* __restrict__ out){
    extern __shared__ float sm[];
    __nv_bfloat16* w2h=(__nv_bfloat16*)(sm+O_W2H);
    __nv_bfloat16* w3h=(__nv_bfloat16*)(sm+O_W3H);
    __nv_bfloat16* ksm=(__nv_bfloat16*)(sm+O_KS);
    __nv_bfloat16* sg =(__nv_bfloat16*)(sm+O_SG);
    float* Zs=sm+O_Z;
    float* pt=sm+O_SG+3*SGF;           // aliased onto sg[3]
    const float* tss=sm+O_TS;

    const int tid=threadIdx.x, wid=tid>>5, lane=tid&31;
    const int gid=lane>>2, tig=lane&3;
    const int wm=(wid&1)*16, wn=((wid>>1)&3)*16, ks2=wid>>3;
    const int wn8=((wid>>1)&1)*8, ks4=wid>>2;
    const int rank=blockIdx.x&7, clus=blockIdx.x>>3;
    const int m0=clus*32, n0h=rank*64, n0k=rank*16;
    const uint32_t ks_sma=sma(ksm);
    const uint32_t mb_k=sma(sm+O_MB)+0u;
    const uint32_t mb_y=sma(sm+O_MB)+8u;

    const int sr=tid>>4, sc=(tid&15)<<3;
    uint32_t sgb[4];
#pragma unroll
    for(int i=0;i<4;i++) sgb[i]=sma(sg+i*(32*136)) + (uint32_t)(sr*136+sc)*2u;

    // ---- init ----
    for(int i=tid;i<64*512;i+=NTHR){int n=i>>9,k=i&511;
        w2h[n*520+k]=__float2bfloat16(w2[(size_t)(n0h+n)*WW+k]);}
    for(int i=tid;i<16*512;i+=NTHR){int n=i>>9,k=i&511;
        w3h[n*520+k]=__float2bfloat16(w3[(size_t)(n0k+n)*WW+k]);}
    for(int i=tid;i<64*128;i+=NTHR){int n=i>>7,k=i&127;
        sm[O_W1+n*132+k]=f2tf32(w1[(size_t)(n0h+n)*DD+k]);}
    for(int i=tid;i<16*128;i+=NTHR){int n=i>>7,k=i&127;
        sm[O_AM+n*132+k]=f2tf32(Am[(size_t)(n0k+n)*DD+k]);}
    if(tid<64) sm[O_B+tid]=b1[n0h+tid];
    else if(tid<128) sm[O_B+tid]=b2[n0h+tid-64];
    else if(tid<144) sm[O_B+tid]=b3[n0k+tid-128];
    sm[O_TS+tid]=ts[tid];
    {   int i=rank*NTHR+tid;
        int r=i>>7,c=i&127; float v=yi[(size_t)(m0+r)*DD+c];
        __stcg(g_y+(size_t)(m0+r)*DD+c,v);
        out[(size_t)(m0+r)*TT*DD+c]=v;}
    if(tid==0){ mbinit(mb_k,8); mbinit(mb_y,8); }
    __syncthreads();
    carr(); cwait();

    const float* b1s=sm+O_B; const float* b2s=sm+O_B+64; const float* b3s=sm+O_B+128;
    unsigned ph_k=0, ph_y=0;
    const int zr=tid>>4, zc=(tid&15)<<3;
    const int cg=n0k+wn8+2*tig;
    const int r0g=m0+wm+gid;

    float yreg[8];

    for(int t=0;t<TT-1;t++){
        const float h=tss[t+1]-tss[t];
        float yacc[4]={0.f,0.f,0.f,0.f};
        if(t>0){ mbwait(mb_y,ph_y); ph_y^=1; }
        {   const float4* yp=(const float4*)(g_y+(size_t)(m0+zr)*DD+zc);
            float4 a=__ldcg(yp), b=__ldcg(yp+1);
            yreg[0]=a.x;yreg[1]=a.y;yreg[2]=a.z;yreg[3]=a.w;
            yreg[4]=b.x;yreg[5]=b.y;yreg[6]=b.z;yreg[7]=b.w;}
        for(int s=0;s<6;s++){
            float ha[5];
#pragma unroll
            for(int j=0;j<5;j++) ha[j]=h*c_AT[s][j];
            if(s>0){ mbwait(mb_k,ph_k); ph_k^=1; }

            // ---- Z build: y (regs) + sum ha_j * k_j (bf16 SMEM) -> Zs tf32 ----
            {
                float z[8];
#pragma unroll
                for(int i=0;i<8;i++) z[i]=yreg[i];
                for(int j=0;j<s;j++){
                    float a=ha[j];
                    uint4 kk=*(const uint4*)(ksm + j*4096 + zr*128 + zc);
                    z[0]+=a*__uint_as_float(kk.x<<16);
                    z[1]+=a*__uint_as_float(kk.x&0xFFFF0000u);
                    z[2]+=a*__uint_as_float(kk.y<<16);
                    z[3]+=a*__uint_as_float(kk.y&0xFFFF0000u);
                    z[4]+=a*__uint_as_float(kk.z<<16);
                    z[5]+=a*__uint_as_float(kk.z&0xFFFF0000u);
                    z[6]+=a*__uint_as_float(kk.w<<16);
                    z[7]+=a*__uint_as_float(kk.w&0xFFFF0000u);}
                float* zd=Zs+zr*132+zc;
                *(float4*)zd    =make_float4(f2tf32(z[0]),f2tf32(z[1]),f2tf32(z[2]),f2tf32(z[3]));
                *(float4*)(zd+4)=make_float4(f2tf32(z[4]),f2tf32(z[5]),f2tf32(z[6]),f2tf32(z[7]));
            }
            __syncthreads();

            // ---- G1: H1 = tanh(Z @ w1^T + b1)  tf32 ----
            {
                float acc[2][4]={{0,0,0,0},{0,0,0,0}};
                mmaT16(Zs,132,sm+O_W1,132,acc,wm,wn,ks2*64,lane);
                if(ks2==1){
                    int r0=wm+gid, c=wn+2*tig;
                    *(float2*)(pt+r0*68+c)      =make_float2(acc[0][0],acc[0][1]);
                    *(float2*)(pt+(r0+8)*68+c)  =make_float2(acc[0][2],acc[0][3]);
                    *(float2*)(pt+r0*68+c+8)    =make_float2(acc[1][0],acc[1][1]);
                    *(float2*)(pt+(r0+8)*68+c+8)=make_float2(acc[1][2],acc[1][3]);}
                __syncthreads();
                if(ks2==0){
                    int r0=wm+gid, c=wn+2*tig;
#pragma unroll
                    for(int j=0;j<2;j++){
                        float2 p0=*(float2*)(pt+r0*68+c+8*j);
                        float2 p1=*(float2*)(pt+(r0+8)*68+c+8*j);
                        float bb0=b1s[c+8*j], bb1=b1s[c+8*j+1];
                        int cgl=n0h+c+8*j;
                        unsigned u0=pack_bf2(ftanh(acc[j][0]+p0.x+bb0),ftanh(acc[j][1]+p0.y+bb1));
                        unsigned u1=pack_bf2(ftanh(acc[j][2]+p1.x+bb0),ftanh(acc[j][3]+p1.y+bb1));
                        __stcg((unsigned*)(g_h1+(size_t)(m0+r0)*WW+cgl),u0);
                        __stcg((unsigned*)(g_h1+(size_t)(m0+r0+8)*WW+cgl),u1);}}
            }
            carr(); cwait();   // H1 exchange

            // ---- G2: H2 = tanh(H1 @ w2^T + b2)  bf16, full prefetch ----
            {
#pragma unroll
                for(int ck=0;ck<4;ck++){
                    cpa(sgb[ck], g_h1+(size_t)(m0+sr)*WW+ck*128+sc); cpc();}
                float acc[2][4]={{0,0,0,0},{0,0,0,0}};
#pragma unroll
                for(int ck=0;ck<4;ck++){
                    if(ck==0)      asm volatile("cp.async.wait_group 3;":::"memory");
                    else if(ck==1) asm volatile("cp.async.wait_group 2;":::"memory");
                    else if(ck==2) asm volatile("cp.async.wait_group 1;":::"memory");
                    else           asm volatile("cp.async.wait_group 0;":::"memory");
                    __syncthreads();
                    mmaB16(sg+ck*(32*136),136,w2h,520,acc,wm,wn,ks2*64,ck*128+ks2*64,lane,4);}
                __syncthreads();   // protect sg[3] (=pt)
                if(ks2==1){
                    int r0=wm+gid, c=wn+2*tig;
                    *(float2*)(pt+r0*68+c)      =make_float2(acc[0][0],acc[0][1]);
                    *(float2*)(pt+(r0+8)*68+c)  =make_float2(acc[0][2],acc[0][3]);
                    *(float2*)(pt+r0*68+c+8)    =make_float2(acc[1][0],acc[1][1]);
                    *(float2*)(pt+(r0+8)*68+c+8)=make_float2(acc[1][2],acc[1][3]);}
                __syncthreads();
                if(ks2==0){
                    int r0=wm+gid, c=wn+2*tig;
#pragma unroll
                    for(int j=0;j<2;j++){
                        float2 p0=*(float2*)(pt+r0*68+c+8*j);
                        float2 p1=*(float2*)(pt+(r0+8)*68+c+8*j);
                        float bb0=b2s[c+8*j], bb1=b2s[c+8*j+1];
                        int cgl=n0h+c+8*j;
                        unsigned u0=pack_bf2(ftanh(acc[j][0]+p0.x+bb0),ftanh(acc[j][1]+p0.y+bb1));
                        unsigned u1=pack_bf2(ftanh(acc[j][2]+p1.x+bb0),ftanh(acc[j][3]+p1.y+bb1));
                        __stcg((unsigned*)(g_h2+(size_t)(m0+r0)*WW+cgl),u0);
                        __stcg((unsigned*)(g_h2+(size_t)(m0+r0+8)*WW+cgl),u1);}}
            }
            carr();                       // split-phase: release H2 early

            // ---- G3 local part while peers catch up: Z @ A^T (tf32) ----
            float acc3[4]={0,0,0,0};
            mmaT8(Zs,132,sm+O_AM,132,acc3,wm,wn8,ks4*32,lane);
            cwait();                      // peers' H2 now visible

            // ---- G3: += H2 @ w3^T  (bf16) ----
            {
#pragma unroll
                for(int ck=0;ck<4;ck++){
                    cpa(sgb[ck], g_h2+(size_t)(m0+sr)*WW+ck*128+sc); cpc();}
                float2 yo0, yo1;
                if(s==5 && ks4==0){
                    yo0=__ldcg((const float2*)(g_y+(size_t)r0g*DD+cg));
                    yo1=__ldcg((const float2*)(g_y+(size_t)(r0g+8)*DD+cg));}
#pragma unroll
                for(int ck=0;ck<4;ck++){
                    if(ck==0)      asm volatile("cp.async.wait_group 3;":::"memory");
                    else if(ck==1) asm volatile("cp.async.wait_group 2;":::"memory");
                    else if(ck==2) asm volatile("cp.async.wait_group 1;":::"memory");
                    else           asm volatile("cp.async.wait_group 0;":::"memory");
                    __syncthreads();
                    mmaB8(sg+ck*(32*136),136,w3h,520,acc3,wm,wn8,ks4*32,ck*128+ks4*32,lane,2);}
                __syncthreads();   // protect sg[3] (=pt)
                if(ks4>0){
                    float* pr=pt+(ks4-1)*512;
                    int r0=wm+gid, c=wn8+2*tig;
                    *(float2*)(pr+r0*16+c)    =make_float2(acc3[0],acc3[1]);
                    *(float2*)(pr+(r0+8)*16+c)=make_float2(acc3[2],acc3[3]);}
                __syncthreads();
                if(ks4==0){
                    int r0=wm+gid, c=wn8+2*tig;
#pragma unroll
                    for(int p=0;p<3;p++){
                        float* pr=pt+p*512;
                        float2 q0=*(float2*)(pr+r0*16+c);
                        float2 q1=*(float2*)(pr+(r0+8)*16+c);
                        acc3[0]+=q0.x; acc3[1]+=q0.y; acc3[2]+=q1.x; acc3[3]+=q1.y;}
                    float bb0=b3s[cg-n0k], bb1=b3s[cg-n0k+1];
                    float kv[4];
                    kv[0]=acc3[0]+bb0; kv[1]=acc3[1]+bb1;
                    kv[2]=acc3[2]+bb0; kv[3]=acc3[3]+bb1;
                    if(s<5){
                        float bs=c_BT[s];
#pragma unroll
                        for(int i=0;i<4;i++) yacc[i]+=bs*kv[i];
#pragma unroll
                        for(int e=0;e<2;e++){
                            int lr=wm+gid+e*8;
                            unsigned kp=pack_bf2(kv[2*e],kv[2*e+1]);
                            uint32_t la=ks_sma + (uint32_t)((s<<12)+lr*128+cg)*2u;
#pragma unroll
                            for(unsigned rr=0;rr<8;rr++) stclu(la,rr,kp);}
                        asm volatile("bar.sync 1,128;":::"memory");
                        if(tid==0){ fgpu();
#pragma unroll
                            for(unsigned rr=0;rr<8;rr++) mbarr_remote(mb_k,rr);}
                    }else{
                        float b5=c_BT[5];
                        float y0=yo0.x+h*(yacc[0]+b5*kv[0]);
                        float y1=yo0.y+h*(yacc[1]+b5*kv[1]);
                        float y2=yo1.x+h*(yacc[2]+b5*kv[2]);
                        float y3=yo1.y+h*(yacc[3]+b5*kv[3]);
                        __stcg((float2*)(g_y+(size_t)r0g*DD+cg),make_float2(y0,y1));
                        __stcg((float2*)(g_y+(size_t)(r0g+8)*DD+cg),make_float2(y2,y3));
                        *(float2*)(out+(size_t)r0g*TT*DD+(size_t)(t+1)*DD+cg)
                            =make_float2(y0,y1);
                        *(float2*)(out+(size_t)(r0g+8)*TT*DD+(size_t)(t+1)*DD+cg)
                            =make_float2(y2,y3);
                        asm volatile("bar.sync 1,128;":::"memory");
                        if(tid==0){ fgpu();
#pragma unroll
                            for(unsigned rr=0;rr<8;rr++) mbarr_remote(mb_y,rr);}
                    }
                }
                // warps with ks4>0 fall through; next stage is gated by mb_k/mb_y
            }
        }
    }
    // No CTA may exit while peers' remote SMEM stores/arrives are in flight.
    carr(); cwait();
}

extern "C" void kernel_launch(void* const* d_in,const int* in_sizes,int n_in,
                              void* d_out,int out_size){
    (void)in_sizes;(void)n_in;(void)out_size;
    cudaFuncSetAttribute(ode_kernel,cudaFuncAttributeMaxDynamicSharedMemorySize,SMF*4);
    cudaLaunchConfig_t cfg={};
    cfg.gridDim=dim3(128,1,1);
    cfg.blockDim=dim3(NTHR,1,1);
    cfg.dynamicSmemBytes=SMF*4;
    cudaLaunchAttribute at[1];
    at[0].id=cudaLaunchAttributeClusterDimension;
    at[0].val.clusterDim.x=8; at[0].val.clusterDim.y=1; at[0].val.clusterDim.z=1;
    cfg.attrs=at; cfg.numAttrs=1;
    cudaLaunchKernelEx(&cfg,ode_kernel,
        (const float*)d_in[0],(const float*)d_in[1],(const float*)d_in[2],
        (const float*)d_in[3],(const float*)d_in[4],(const float*)d_in[5],
        (const float*)d_in[6],(const float*)d_in[7],(const float*)d_in[8],
        (float*)d_out);
}